// round 9
// baseline (speedup 1.0000x reference)
#include <cuda_runtime.h>
#include <cstdint>

// VectorQuant: N=8, S=2048, C=4, K=512, V=64
// Persistent-ish: 128 CTAs (one wave), each owns one c and 4 M-tiles of 128 rows.
// B (codebook) loaded to smem once per CTA; A prefetched via cp.async.
// Scores via tcgen05 kind::tf32 MMA; single TMEM sweep with running-min
// candidate list; exact-fp32 rescore of candidates. SIMT fallback for the
// non-sm_103a compile pass.
// d_out layout: [out0: 8*2048*4*64][out1: 8*2048*4][out2: 8*2048*4]

#if defined(__CUDA_ARCH__) && (defined(__CUDA_ARCH_FEAT_SM103_ALL) || \
    (defined(__CUDA_ARCH_SPECIFIC__) && __CUDA_ARCH_SPECIFIC__ == 1030))
#define VQ_TC 1
#else
#define VQ_TC 0
#endif

#define NS     16384
#define CC     4
#define KK     512
#define VV     64
#define TPB    256
#define MTILE  128
#define NHALF  256
#define TILES  4
#define MARGIN 0.5f
#define NCAND  12

// byte offsets in dynamic smem
#define SB_B     0         // 131072: B in two 64KB halves (256 rows x 128B), atom-blocked SW128
#define SB_A     131072    // 2 x 32768: A double buffer (128 rows x 256B), atom-blocked SW128
#define SB_E2    196608    // 512 floats: ||e_k||^2 (exact fp32)
#define SB_RED   198656    // 2 groups x 128 rows x 8B: (float d, int k)
#define SB_TPTR  200704    // tmem base ptr
#define SB_MBAR  200712    // 2 x 8B mbarriers
#define SB_TOTAL 200832

static constexpr uint32_t IDESC_TF32 =
    (1u << 4)              // dtype = F32
    | (2u << 7)            // atype = TF32
    | (2u << 10)           // btype = TF32
    | ((NHALF / 8) << 17)  // N = 256
    | ((MTILE / 16) << 24);// M = 128

static constexpr uint64_t DESC_BASE_SW128 =
    (uint64_t(2) << 61) | (uint64_t(1) << 46) | (uint64_t(64) << 32) | (uint64_t(1) << 16);

__device__ __forceinline__ uint32_t smem_u32(const void* p) {
    uint32_t a;
    asm("{ .reg .u64 t; cvta.to.shared.u64 t, %1; cvt.u32.u64 %0, t; }" : "=r"(a) : "l"(p));
    return a;
}

// Swizzled byte offset of element (row, vbyte) in an atom-blocked SW128 tile.
// atom = 8 rows x 128B; atoms stacked row-major first (atomrows of them), then col.
__device__ __forceinline__ uint32_t swz(int row, int vbyte, int atomrows) {
    uint32_t b = (uint32_t)(((row >> 3) + (vbyte >> 7) * atomrows) * 1024
                            + (row & 7) * 128 + (vbyte & 127));
    return b ^ ((b >> 3) & 0x70);
}

// Exact fp32 distance (minus the row-constant x^2): e2[k] - 2 * x[row].e[k]
__device__ __forceinline__ float exact_d(const char* smem, const float* e2,
                                         int abuf, int row, int k) {
    const char* aa = smem + SB_A + abuf * 32768;
    const char* bb = smem + SB_B + (k >> 8) * 65536;
    int brow = k & 255;
    float d0 = 0.f, d1 = 0.f, d2 = 0.f, d3 = 0.f;
    #pragma unroll
    for (int v4 = 0; v4 < 16; v4++) {
        float4 xv = *(const float4*)(aa + swz(row, v4 * 16, 16));
        float4 ev = *(const float4*)(bb + swz(brow, v4 * 16, 32));
        d0 = fmaf(xv.x, ev.x, d0);
        d1 = fmaf(xv.y, ev.y, d1);
        d2 = fmaf(xv.z, ev.z, d2);
        d3 = fmaf(xv.w, ev.w, d3);
    }
    return e2[k] - 2.0f * ((d0 + d1) + (d2 + d3));
}

__device__ __forceinline__ void upd_best(float d, int k, float& bd, int& bk) {
    if (d < bd || (d == bd && k < bk)) { bd = d; bk = k; }
}

#if VQ_TC
__device__ __forceinline__ uint32_t elect_one() {
    uint32_t pred;
    asm volatile("{\n\t.reg .pred p;\n\telect.sync _|p, 0xFFFFFFFF;\n\t"
                 "selp.b32 %0, 1, 0, p;\n\t}" : "=r"(pred));
    return pred;
}

__device__ __forceinline__ void mma_tf32_ss(uint32_t d_tmem, uint64_t a_desc,
                                            uint64_t b_desc, uint32_t idesc, bool en) {
    uint32_t e = en ? 1u : 0u;
    uint32_t z = 0u;
    asm volatile(
        "{\n\t.reg .pred p;\n\t"
        "setp.ne.u32 p, %5, 0;\n\t"
        "tcgen05.mma.cta_group::1.kind::tf32 [%0], %1, %2, %3, {%4, %4, %4, %4}, p;\n\t}"
        :: "r"(d_tmem), "l"(a_desc), "l"(b_desc), "r"(idesc), "r"(z), "r"(e)
        : "memory");
}

#define LDTM_X32(r, addr)                                                     \
    asm volatile("tcgen05.ld.sync.aligned.32x32b.x32.b32 "                    \
        "{%0, %1, %2, %3, %4, %5, %6, %7, %8, %9, %10, %11, %12, %13, %14, %15, " \
        " %16, %17, %18, %19, %20, %21, %22, %23, %24, %25, %26, %27, %28, %29, %30, %31}, [%32];" \
        : "=r"((r)[0]), "=r"((r)[1]), "=r"((r)[2]), "=r"((r)[3]),             \
          "=r"((r)[4]), "=r"((r)[5]), "=r"((r)[6]), "=r"((r)[7]),             \
          "=r"((r)[8]), "=r"((r)[9]), "=r"((r)[10]), "=r"((r)[11]),           \
          "=r"((r)[12]), "=r"((r)[13]), "=r"((r)[14]), "=r"((r)[15]),         \
          "=r"((r)[16]), "=r"((r)[17]), "=r"((r)[18]), "=r"((r)[19]),         \
          "=r"((r)[20]), "=r"((r)[21]), "=r"((r)[22]), "=r"((r)[23]),         \
          "=r"((r)[24]), "=r"((r)[25]), "=r"((r)[26]), "=r"((r)[27]),         \
          "=r"((r)[28]), "=r"((r)[29]), "=r"((r)[30]), "=r"((r)[31])          \
        : "r"(addr))

__device__ __forceinline__ void mbar_wait_parity(uint32_t mbar, uint32_t parity) {
    uint32_t done;
    asm volatile(
        "{\n\t.reg .pred p;\n\t"
        "mbarrier.try_wait.parity.acquire.cta.shared::cta.b64 p, [%1], %2;\n\t"
        "selp.b32 %0, 1, 0, p;\n\t}"
        : "=r"(done) : "r"(mbar), "r"(parity) : "memory");
    if (!done) {
        asm volatile(
            "{\n\t.reg .pred P1;\n\t"
            "WAIT_LOOP_%=:\n\t"
            "mbarrier.try_wait.parity.acquire.cta.shared::cta.b64 P1, [%0], %1, 0x989680;\n\t"
            "@P1 bra.uni WAIT_DONE_%=;\n\t"
            "bra.uni WAIT_LOOP_%=;\n\t"
            "WAIT_DONE_%=:\n\t}"
            :: "r"(mbar), "r"(parity) : "memory");
    }
}
#endif  // VQ_TC

__device__ __forceinline__ void cp_async16(uint32_t dst, const void* src) {
    asm volatile("cp.async.cg.shared.global [%0], [%1], 16;"
                 :: "r"(dst), "l"(src) : "memory");
}

extern __shared__ __align__(1024) float smem_dyn[];

__global__ void __launch_bounds__(TPB, 1)
vq_tc_kernel(const float* __restrict__ x, const float* __restrict__ emb,
             float* __restrict__ out0, float* __restrict__ out1,
             float* __restrict__ out2)
{
    char* smem = (char*)smem_dyn;
    const uint32_t smem_base = smem_u32(smem);
    float* e2 = (float*)(smem + SB_E2);
    const int tid = threadIdx.x;
    const int wid = tid >> 5;
    const int lid = tid & 31;
    const int w   = wid & 3;       // TMEM lane partition
    const int g   = wid >> 2;      // col half: cols [g*256, g*256+256)
    const int row = w * 32 + lid;  // row owned in sweep

    const int c  = blockIdx.y;
    const float* ec = emb + (size_t)c * KK * VV;
    const int tile0 = blockIdx.x * TILES;

#if VQ_TC
    const uint32_t mbar0 = smem_base + SB_MBAR;
    if (wid == 0) {
        asm volatile("tcgen05.alloc.cta_group::1.sync.aligned.shared::cta.b32 [%0], %1;"
                     :: "r"(smem_base + SB_TPTR), "r"(512u) : "memory");
        asm volatile("tcgen05.relinquish_alloc_permit.cta_group::1.sync.aligned;");
    }
    if (tid == 0) {
        asm volatile("mbarrier.init.shared.b64 [%0], %1;" :: "r"(mbar0), "r"(1u) : "memory");
        asm volatile("mbarrier.init.shared.b64 [%0], %1;" :: "r"(mbar0 + 8), "r"(1u) : "memory");
    }
#endif

    // ---- Setup: B (512x64) into two atom-blocked SW128 halves ----
    {
        const float4* ec4 = (const float4*)ec;
        #pragma unroll
        for (int it = 0; it < 32; it++) {
            int idx = it * TPB + tid;          // 0..8191 float4s
            int k = idx >> 4;
            int j = idx & 15;
            float4 v = ec4[idx];
            uint32_t off = SB_B + (k >> 8) * 65536 + swz(k & 255, j * 16, 32);
            *(float4*)(smem + off) = v;
        }
    }
    // ---- e2[k] exact fp32 (2 rows per thread) ----
    #pragma unroll
    for (int j = 0; j < 2; j++) {
        int k = tid + j * TPB;
        const float4* rp = (const float4*)(ec + (size_t)k * VV);
        float s = 0.f;
        #pragma unroll
        for (int i = 0; i < VV / 4; i++) {
            float4 v = rp[i];
            s += v.x * v.x + v.y * v.y + v.z * v.z + v.w * v.w;
        }
        e2[k] = s;
    }
    // ---- A(0) via cp.async ----
    {
        int rowbase = tile0 * MTILE;
        #pragma unroll
        for (int it = 0; it < 8; it++) {
            int idx = it * TPB + tid;          // 0..2047 float4s
            int r = idx >> 4;
            int j = idx & 15;
            const float* src = x + ((size_t)(rowbase + r) * CC + c) * VV + j * 4;
            cp_async16(smem_base + SB_A + swz(r, j * 16, 16), src);
        }
        asm volatile("cp.async.commit_group;" ::: "memory");
        asm volatile("cp.async.wait_group 0;" ::: "memory");
    }
    asm volatile("fence.proxy.async.shared::cta;" ::: "memory");
    __syncthreads();

#if VQ_TC
    uint32_t tmem_base;
    asm volatile("ld.shared.b32 %0, [%1];" : "=r"(tmem_base) : "r"(smem_base + SB_TPTR));
#endif

    for (int t = 0; t < TILES; t++) {
        const int abuf = t & 1;
        const int rglob0 = (tile0 + t) * MTILE;

#if VQ_TC
        // ---- MMA: D[128,512] = A.B^T (tf32), two N-halves, each commits a mbar ----
        if (wid == 0 && elect_one()) {
            const uint64_t a_base = DESC_BASE_SW128 |
                (((smem_base + SB_A + abuf * 32768) >> 4) & 0x3FFF);
            const uint32_t offA[8] = {0, 2, 4, 6, 1024, 1026, 1028, 1030};
            const uint32_t offB[8] = {0, 2, 4, 6, 2048, 2050, 2052, 2054};
            #pragma unroll
            for (int h = 0; h < 2; h++) {
                const uint64_t b_base = DESC_BASE_SW128 |
                    (((smem_base + SB_B + h * 65536) >> 4) & 0x3FFF);
                #pragma unroll
                for (int s = 0; s < 8; s++) {
                    mma_tf32_ss(tmem_base + h * NHALF, a_base + offA[s],
                                b_base + offB[s], IDESC_TF32, s > 0);
                }
                asm volatile(
                    "tcgen05.commit.cta_group::1.mbarrier::arrive::one.shared::cluster.b64 [%0];"
                    :: "r"(mbar0 + 8u * h) : "memory");
            }
        }
#endif

        // ---- Prefetch A(t+1) into the other buffer (overlaps MMA + sweep) ----
        if (t + 1 < TILES) {
            int nbuf = (t + 1) & 1;
            int rowbase = (tile0 + t + 1) * MTILE;
            #pragma unroll
            for (int it = 0; it < 8; it++) {
                int idx = it * TPB + tid;
                int r = idx >> 4;
                int j = idx & 15;
                const float* src = x + ((size_t)(rowbase + r) * CC + c) * VV + j * 4;
                cp_async16(smem_base + SB_A + nbuf * 32768 + swz(r, j * 16, 16), src);
            }
            asm volatile("cp.async.commit_group;" ::: "memory");
        }

        float bd = 3.4e38f;
        int bk = 1 << 30;

#if VQ_TC
        mbar_wait_parity(mbar0 + 8u * g, (uint32_t)(t & 1));
        asm volatile("tcgen05.fence::after_thread_sync;" ::: "memory");

        // ---- Single sweep: 8 chunks of 32 cols; running-min candidate list ----
        int cand[NCAND];
        int ncand = 0;
        float runmin = 3.4e38f;
        const int colbase = g * NHALF;
        #pragma unroll
        for (int j = 0; j < 8; j++) {
            uint32_t r32[32];
            LDTM_X32(r32, tmem_base + colbase + j * 32);
            asm volatile("tcgen05.wait::ld.sync.aligned;" ::: "memory");
            float sv[32];
            float m0 = 3.4e38f, m1 = 3.4e38f, m2 = 3.4e38f, m3 = 3.4e38f;
            #pragma unroll
            for (int i = 0; i < 32; i += 4) {
                int k = colbase + j * 32 + i;
                sv[i]     = fmaf(-2.0f, __uint_as_float(r32[i]),     e2[k]);
                sv[i + 1] = fmaf(-2.0f, __uint_as_float(r32[i + 1]), e2[k + 1]);
                sv[i + 2] = fmaf(-2.0f, __uint_as_float(r32[i + 2]), e2[k + 2]);
                sv[i + 3] = fmaf(-2.0f, __uint_as_float(r32[i + 3]), e2[k + 3]);
                m0 = fminf(m0, sv[i]);
                m1 = fminf(m1, sv[i + 1]);
                m2 = fminf(m2, sv[i + 2]);
                m3 = fminf(m3, sv[i + 3]);
            }
            runmin = fminf(runmin, fminf(fminf(m0, m1), fminf(m2, m3)));
            float thr = runmin + MARGIN;
            #pragma unroll
            for (int i = 0; i < 32; i++) {
                if (sv[i] < thr) {
                    int k = colbase + j * 32 + i;
                    if (ncand < NCAND) cand[ncand++] = k;
                    else upd_best(exact_d(smem, e2, abuf, row, k), k, bd, bk);
                }
            }
        }
        asm volatile("tcgen05.fence::before_thread_sync;" ::: "memory");

        // ---- Exact rescore of candidates (superset; tie rule order-independent) ----
        for (int i = 0; i < ncand; i++) {
            int k = cand[i];
            upd_best(exact_d(smem, e2, abuf, row, k), k, bd, bk);
        }
#else
        // ---- SIMT fallback: exact scan of this (g,row)'s 256 cols ----
        for (int kk = 0; kk < NHALF; kk++) {
            int k = g * NHALF + kk;
            upd_best(exact_d(smem, e2, abuf, row, k), k, bd, bk);
        }
#endif

        *(float*)(smem + SB_RED + (g * MTILE + row) * 8) = bd;
        *(int*)(smem + SB_RED + (g * MTILE + row) * 8 + 4) = bk;
        __syncthreads();

        // ---- Combine halves + epilogue: 2 threads per row ----
        {
            const int rw = tid >> 1;       // row 0..127
            const int half = tid & 1;      // which 32-element half of the vector
            float d0v = *(float*)(smem + SB_RED + rw * 8);
            int k0v = *(int*)(smem + SB_RED + rw * 8 + 4);
            float d1v = *(float*)(smem + SB_RED + (MTILE + rw) * 8);
            int k1v = *(int*)(smem + SB_RED + (MTILE + rw) * 8 + 4);
            upd_best(d1v, k1v, d0v, k0v);
            const int bkr = k0v;

            const char* aa = smem + SB_A + abuf * 32768;
            const char* bb = smem + SB_B + (bkr >> 8) * 65536;
            const int brow = bkr & 255;
            const int rglob = rglob0 + rw;
            float4* o0 = (float4*)(out0 + ((size_t)rglob * CC + c) * VV) + half * 8;
            float ss = 0.f;
            #pragma unroll
            for (int i = 0; i < 8; i++) {
                int vb = (half * 8 + i) * 16;
                float4 xv = *(const float4*)(aa + swz(rw, vb, 16));
                float4 ev = *(const float4*)(bb + swz(brow, vb, 32));
                float q0 = xv.x - ev.x;
                float q1 = xv.y - ev.y;
                float q2 = xv.z - ev.z;
                float q3 = xv.w - ev.w;
                ss += q0 * q0 + q1 * q1 + q2 * q2 + q3 * q3;
                o0[i] = ev;
            }
            ss += __shfl_xor_sync(0xffffffffu, ss, 1);
            if (half == 0) {
                out1[(size_t)rglob * CC + c] = ss;
                out2[(size_t)rglob * CC + c] = ss;
            }
        }

        // ---- Tile boundary: A(t+1) ready, everyone done with TMEM/RED ----
        if (t + 1 < TILES)
            asm volatile("cp.async.wait_group 0;" ::: "memory");
        __syncthreads();
        asm volatile("fence.proxy.async.shared::cta;" ::: "memory");
    }

#if VQ_TC
    if (wid == 0) {
        asm volatile("tcgen05.dealloc.cta_group::1.sync.aligned.b32 %0, %1;"
                     :: "r"(tmem_base), "r"(512u));
    }
#endif
}

extern "C" void kernel_launch(void* const* d_in, const int* in_sizes, int n_in,
                              void* d_out, int out_size) {
    const float* x   = (const float*)d_in[0];
    const float* emb = (const float*)d_in[1];
    float* out  = (float*)d_out;
    float* out0 = out;
    float* out1 = out + (size_t)NS * CC * VV;
    float* out2 = out1 + (size_t)NS * CC;

    cudaFuncSetAttribute(vq_tc_kernel, cudaFuncAttributeMaxDynamicSharedMemorySize,
                         SB_TOTAL);
    dim3 grid(NS / (MTILE * TILES), CC);
    vq_tc_kernel<<<grid, TPB, SB_TOTAL>>>(x, emb, out0, out1, out2);
}

// round 11
// speedup vs baseline: 3.8906x; 3.8906x over previous
#include <cuda_runtime.h>
#include <cstdint>

// VectorQuant: N=8, S=2048, C=4, K=512, V=64
// 128 CTAs (one wave), each owns one c and 4 M-tiles of 128 rows.
// B (codebook) in smem once per CTA; A double-buffered via cp.async.
// Scores via tcgen05 kind::tf32 MMA; single compact TMEM sweep with
// running-min + candidate bitmask, exact-fp32 rescore per chunk.
// SIMT fallback for the non-sm_103a compile pass.
// d_out layout: [out0: 8*2048*4*64][out1: 8*2048*4][out2: 8*2048*4]

#if defined(__CUDA_ARCH__) && (defined(__CUDA_ARCH_FEAT_SM103_ALL) || \
    (defined(__CUDA_ARCH_SPECIFIC__) && __CUDA_ARCH_SPECIFIC__ == 1030))
#define VQ_TC 1
#else
#define VQ_TC 0
#endif

#define NS     16384
#define CC     4
#define KK     512
#define VV     64
#define TPB    256
#define MTILE  128
#define NHALF  256
#define TILES  4
#define MARGIN 0.5f

// byte offsets in dynamic smem
#define SB_B     0         // 131072: B in two 64KB halves (256 rows x 128B), atom-blocked SW128
#define SB_A     131072    // 2 x 32768: A double buffer (128 rows x 256B), atom-blocked SW128
#define SB_E2    196608    // 512 floats: ||e_k||^2 (exact fp32)
#define SB_RED   198656    // 2 groups x 128 rows x 8B: (float d, int k)
#define SB_TPTR  200704    // tmem base ptr
#define SB_MBAR  200712    // 2 x 8B mbarriers
#define SB_TOTAL 200832

static constexpr uint32_t IDESC_TF32 =
    (1u << 4)              // dtype = F32
    | (2u << 7)            // atype = TF32
    | (2u << 10)           // btype = TF32
    | ((NHALF / 8) << 17)  // N = 256
    | ((MTILE / 16) << 24);// M = 128

static constexpr uint64_t DESC_BASE_SW128 =
    (uint64_t(2) << 61) | (uint64_t(1) << 46) | (uint64_t(64) << 32) | (uint64_t(1) << 16);

__device__ __forceinline__ uint32_t smem_u32(const void* p) {
    uint32_t a;
    asm("{ .reg .u64 t; cvta.to.shared.u64 t, %1; cvt.u32.u64 %0, t; }" : "=r"(a) : "l"(p));
    return a;
}

// Swizzled byte offset of element (row, vbyte) in an atom-blocked SW128 tile.
__device__ __forceinline__ uint32_t swz(int row, int vbyte, int atomrows) {
    uint32_t b = (uint32_t)(((row >> 3) + (vbyte >> 7) * atomrows) * 1024
                            + (row & 7) * 128 + (vbyte & 127));
    return b ^ ((b >> 3) & 0x70);
}

// Exact fp32 distance (minus the row-constant x^2): e2[k] - 2 * x[row].e[k]
__device__ __forceinline__ float exact_d(const char* smem, const float* e2,
                                         int abuf, int row, int k) {
    const char* aa = smem + SB_A + abuf * 32768;
    const char* bb = smem + SB_B + (k >> 8) * 65536;
    int brow = k & 255;
    float d0 = 0.f, d1 = 0.f, d2 = 0.f, d3 = 0.f;
    #pragma unroll
    for (int v4 = 0; v4 < 16; v4++) {
        float4 xv = *(const float4*)(aa + swz(row, v4 * 16, 16));
        float4 ev = *(const float4*)(bb + swz(brow, v4 * 16, 32));
        d0 = fmaf(xv.x, ev.x, d0);
        d1 = fmaf(xv.y, ev.y, d1);
        d2 = fmaf(xv.z, ev.z, d2);
        d3 = fmaf(xv.w, ev.w, d3);
    }
    return e2[k] - 2.0f * ((d0 + d1) + (d2 + d3));
}

__device__ __forceinline__ void upd_best(float d, int k, float& bd, int& bk) {
    if (d < bd || (d == bd && k < bk)) { bd = d; bk = k; }
}

#if VQ_TC
__device__ __forceinline__ uint32_t elect_one() {
    uint32_t pred;
    asm volatile("{\n\t.reg .pred p;\n\telect.sync _|p, 0xFFFFFFFF;\n\t"
                 "selp.b32 %0, 1, 0, p;\n\t}" : "=r"(pred));
    return pred;
}

__device__ __forceinline__ void mma_tf32_ss(uint32_t d_tmem, uint64_t a_desc,
                                            uint64_t b_desc, uint32_t idesc, bool en) {
    uint32_t e = en ? 1u : 0u;
    uint32_t z = 0u;
    asm volatile(
        "{\n\t.reg .pred p;\n\t"
        "setp.ne.u32 p, %5, 0;\n\t"
        "tcgen05.mma.cta_group::1.kind::tf32 [%0], %1, %2, %3, {%4, %4, %4, %4}, p;\n\t}"
        :: "r"(d_tmem), "l"(a_desc), "l"(b_desc), "r"(idesc), "r"(z), "r"(e)
        : "memory");
}

#define LDTM_X32(r, addr)                                                     \
    asm volatile("tcgen05.ld.sync.aligned.32x32b.x32.b32 "                    \
        "{%0, %1, %2, %3, %4, %5, %6, %7, %8, %9, %10, %11, %12, %13, %14, %15, " \
        " %16, %17, %18, %19, %20, %21, %22, %23, %24, %25, %26, %27, %28, %29, %30, %31}, [%32];" \
        : "=r"((r)[0]), "=r"((r)[1]), "=r"((r)[2]), "=r"((r)[3]),             \
          "=r"((r)[4]), "=r"((r)[5]), "=r"((r)[6]), "=r"((r)[7]),             \
          "=r"((r)[8]), "=r"((r)[9]), "=r"((r)[10]), "=r"((r)[11]),           \
          "=r"((r)[12]), "=r"((r)[13]), "=r"((r)[14]), "=r"((r)[15]),         \
          "=r"((r)[16]), "=r"((r)[17]), "=r"((r)[18]), "=r"((r)[19]),         \
          "=r"((r)[20]), "=r"((r)[21]), "=r"((r)[22]), "=r"((r)[23]),         \
          "=r"((r)[24]), "=r"((r)[25]), "=r"((r)[26]), "=r"((r)[27]),         \
          "=r"((r)[28]), "=r"((r)[29]), "=r"((r)[30]), "=r"((r)[31])          \
        : "r"(addr))

__device__ __forceinline__ void mbar_wait_parity(uint32_t mbar, uint32_t parity) {
    uint32_t done;
    asm volatile(
        "{\n\t.reg .pred p;\n\t"
        "mbarrier.try_wait.parity.acquire.cta.shared::cta.b64 p, [%1], %2;\n\t"
        "selp.b32 %0, 1, 0, p;\n\t}"
        : "=r"(done) : "r"(mbar), "r"(parity) : "memory");
    if (!done) {
        asm volatile(
            "{\n\t.reg .pred P1;\n\t"
            "WAIT_LOOP_%=:\n\t"
            "mbarrier.try_wait.parity.acquire.cta.shared::cta.b64 P1, [%0], %1, 0x989680;\n\t"
            "@P1 bra.uni WAIT_DONE_%=;\n\t"
            "bra.uni WAIT_LOOP_%=;\n\t"
            "WAIT_DONE_%=:\n\t}"
            :: "r"(mbar), "r"(parity) : "memory");
    }
}
#endif  // VQ_TC

__device__ __forceinline__ void cp_async16(uint32_t dst, const void* src) {
    asm volatile("cp.async.cg.shared.global [%0], [%1], 16;"
                 :: "r"(dst), "l"(src) : "memory");
}

extern __shared__ __align__(1024) float smem_dyn[];

__global__ void __launch_bounds__(TPB, 1)
vq_tc_kernel(const float* __restrict__ x, const float* __restrict__ emb,
             float* __restrict__ out0, float* __restrict__ out1,
             float* __restrict__ out2)
{
    char* smem = (char*)smem_dyn;
    const uint32_t smem_base = smem_u32(smem);
    float* e2 = (float*)(smem + SB_E2);
    const int tid = threadIdx.x;
    const int wid = tid >> 5;
    const int lid = tid & 31;
    const int w   = wid & 3;       // TMEM lane partition
    const int g   = wid >> 2;      // col half: cols [g*256, g*256+256)
    const int row = w * 32 + lid;  // row owned in sweep

    const int c  = blockIdx.y;
    const float* ec = emb + (size_t)c * KK * VV;
    const int tile0 = blockIdx.x * TILES;

#if VQ_TC
    const uint32_t mbar0 = smem_base + SB_MBAR;
    if (wid == 0) {
        asm volatile("tcgen05.alloc.cta_group::1.sync.aligned.shared::cta.b32 [%0], %1;"
                     :: "r"(smem_base + SB_TPTR), "r"(512u) : "memory");
        asm volatile("tcgen05.relinquish_alloc_permit.cta_group::1.sync.aligned;");
    }
    if (tid == 0) {
        asm volatile("mbarrier.init.shared.b64 [%0], %1;" :: "r"(mbar0), "r"(1u) : "memory");
        asm volatile("mbarrier.init.shared.b64 [%0], %1;" :: "r"(mbar0 + 8), "r"(1u) : "memory");
    }
#endif

    // ---- Setup: B (512x64) into two atom-blocked SW128 halves ----
    {
        const float4* ec4 = (const float4*)ec;
        for (int it = 0; it < 32; it++) {
            int idx = it * TPB + tid;          // 0..8191 float4s
            int k = idx >> 4;
            int j = idx & 15;
            float4 v = ec4[idx];
            uint32_t off = SB_B + (k >> 8) * 65536 + swz(k & 255, j * 16, 32);
            *(float4*)(smem + off) = v;
        }
    }
    // ---- e2[k] exact fp32 (2 rows per thread) ----
    for (int j = 0; j < 2; j++) {
        int k = tid + j * TPB;
        const float4* rp = (const float4*)(ec + (size_t)k * VV);
        float s = 0.f;
        #pragma unroll
        for (int i = 0; i < VV / 4; i++) {
            float4 v = rp[i];
            s += v.x * v.x + v.y * v.y + v.z * v.z + v.w * v.w;
        }
        e2[k] = s;
    }
    // ---- A(0) via cp.async ----
    {
        int rowbase = tile0 * MTILE;
        for (int it = 0; it < 8; it++) {
            int idx = it * TPB + tid;          // 0..2047 float4s
            int r = idx >> 4;
            int j = idx & 15;
            const float* src = x + ((size_t)(rowbase + r) * CC + c) * VV + j * 4;
            cp_async16(smem_base + SB_A + swz(r, j * 16, 16), src);
        }
        asm volatile("cp.async.commit_group;" ::: "memory");
        asm volatile("cp.async.wait_group 0;" ::: "memory");
    }
    asm volatile("fence.proxy.async.shared::cta;" ::: "memory");
    __syncthreads();

#if VQ_TC
    uint32_t tmem_base;
    asm volatile("ld.shared.b32 %0, [%1];" : "=r"(tmem_base) : "r"(smem_base + SB_TPTR));
#endif

    for (int t = 0; t < TILES; t++) {
        const int abuf = t & 1;
        const int rglob0 = (tile0 + t) * MTILE;

#if VQ_TC
        // ---- MMA: D[128,512] = A.B^T (tf32), two N-halves, each commits a mbar ----
        if (wid == 0 && elect_one()) {
            const uint64_t a_base = DESC_BASE_SW128 |
                (((smem_base + SB_A + abuf * 32768) >> 4) & 0x3FFF);
            const uint32_t offA[8] = {0, 2, 4, 6, 1024, 1026, 1028, 1030};
            const uint32_t offB[8] = {0, 2, 4, 6, 2048, 2050, 2052, 2054};
            #pragma unroll
            for (int h = 0; h < 2; h++) {
                const uint64_t b_base = DESC_BASE_SW128 |
                    (((smem_base + SB_B + h * 65536) >> 4) & 0x3FFF);
                #pragma unroll
                for (int s = 0; s < 8; s++) {
                    mma_tf32_ss(tmem_base + h * NHALF, a_base + offA[s],
                                b_base + offB[s], IDESC_TF32, s > 0);
                }
                asm volatile(
                    "tcgen05.commit.cta_group::1.mbarrier::arrive::one.shared::cluster.b64 [%0];"
                    :: "r"(mbar0 + 8u * h) : "memory");
            }
        }
#endif

        // ---- Prefetch A(t+1) into the other buffer (overlaps MMA + sweep) ----
        if (t + 1 < TILES) {
            int nbuf = (t + 1) & 1;
            int rowbase = (tile0 + t + 1) * MTILE;
            for (int it = 0; it < 8; it++) {
                int idx = it * TPB + tid;
                int r = idx >> 4;
                int j = idx & 15;
                const float* src = x + ((size_t)(rowbase + r) * CC + c) * VV + j * 4;
                cp_async16(smem_base + SB_A + nbuf * 32768 + swz(r, j * 16, 16), src);
            }
            asm volatile("cp.async.commit_group;" ::: "memory");
        }

        float bd = 3.4e38f;
        int bk = 1 << 30;

#if VQ_TC
        mbar_wait_parity(mbar0 + 8u * g, (uint32_t)(t & 1));
        asm volatile("tcgen05.fence::after_thread_sync;" ::: "memory");

        // ---- Compact sweep: 8 chunks of 32 cols (NOT unrolled; small I-footprint).
        // Per chunk: min-pass, threshold, candidate bitmask, immediate exact rescore.
        float runmin = 3.4e38f;
        const int colbase = g * NHALF;
        #pragma unroll 1
        for (int j = 0; j < 8; j++) {
            uint32_t r32[32];
            LDTM_X32(r32, tmem_base + colbase + j * 32);
            asm volatile("tcgen05.wait::ld.sync.aligned;" ::: "memory");
            const int kbase = colbase + j * 32;
            // pass 1: chunk min
            float m0 = 3.4e38f, m1 = 3.4e38f, m2 = 3.4e38f, m3 = 3.4e38f;
            #pragma unroll
            for (int i = 0; i < 32; i += 4) {
                m0 = fminf(m0, fmaf(-2.0f, __uint_as_float(r32[i]),     e2[kbase + i]));
                m1 = fminf(m1, fmaf(-2.0f, __uint_as_float(r32[i + 1]), e2[kbase + i + 1]));
                m2 = fminf(m2, fmaf(-2.0f, __uint_as_float(r32[i + 2]), e2[kbase + i + 2]));
                m3 = fminf(m3, fmaf(-2.0f, __uint_as_float(r32[i + 3]), e2[kbase + i + 3]));
            }
            runmin = fminf(runmin, fminf(fminf(m0, m1), fminf(m2, m3)));
            const float thr = runmin + MARGIN;
            // pass 2: candidate bitmask (recompute scores; superset w.r.t. final thr)
            uint32_t mask = 0u;
            #pragma unroll
            for (int i = 0; i < 32; i++) {
                float s = fmaf(-2.0f, __uint_as_float(r32[i]), e2[kbase + i]);
                if (s < thr) mask |= (1u << i);
            }
            // rescore set bits exactly (ascending i => ascending k)
            while (mask) {
                int i = __ffs(mask) - 1;
                mask &= mask - 1;
                int k = kbase + i;
                upd_best(exact_d(smem, e2, abuf, row, k), k, bd, bk);
            }
        }
        asm volatile("tcgen05.fence::before_thread_sync;" ::: "memory");
#else
        // ---- SIMT fallback: exact scan of this (g,row)'s 256 cols ----
        for (int kk = 0; kk < NHALF; kk++) {
            int k = g * NHALF + kk;
            upd_best(exact_d(smem, e2, abuf, row, k), k, bd, bk);
        }
#endif

        *(float*)(smem + SB_RED + (g * MTILE + row) * 8) = bd;
        *(int*)(smem + SB_RED + (g * MTILE + row) * 8 + 4) = bk;
        __syncthreads();

        // ---- Combine halves + epilogue: 2 threads per row ----
        {
            const int rw = tid >> 1;       // row 0..127
            const int half = tid & 1;      // which 32-element half of the vector
            float d0v = *(float*)(smem + SB_RED + rw * 8);
            int k0v = *(int*)(smem + SB_RED + rw * 8 + 4);
            float d1v = *(float*)(smem + SB_RED + (MTILE + rw) * 8);
            int k1v = *(int*)(smem + SB_RED + (MTILE + rw) * 8 + 4);
            upd_best(d1v, k1v, d0v, k0v);
            const int bkr = k0v;

            const char* aa = smem + SB_A + abuf * 32768;
            const char* bb = smem + SB_B + (bkr >> 8) * 65536;
            const int brow = bkr & 255;
            const int rglob = rglob0 + rw;
            float4* o0 = (float4*)(out0 + ((size_t)rglob * CC + c) * VV) + half * 8;
            float ss = 0.f;
            #pragma unroll
            for (int i = 0; i < 8; i++) {
                int vb = (half * 8 + i) * 16;
                float4 xv = *(const float4*)(aa + swz(rw, vb, 16));
                float4 ev = *(const float4*)(bb + swz(brow, vb, 32));
                float q0 = xv.x - ev.x;
                float q1 = xv.y - ev.y;
                float q2 = xv.z - ev.z;
                float q3 = xv.w - ev.w;
                ss += q0 * q0 + q1 * q1 + q2 * q2 + q3 * q3;
                o0[i] = ev;
            }
            ss += __shfl_xor_sync(0xffffffffu, ss, 1);
            if (half == 0) {
                out1[(size_t)rglob * CC + c] = ss;
                out2[(size_t)rglob * CC + c] = ss;
            }
        }

        // ---- Tile boundary: A(t+1) ready, everyone done with TMEM/RED ----
        if (t + 1 < TILES)
            asm volatile("cp.async.wait_group 0;" ::: "memory");
        __syncthreads();
        asm volatile("fence.proxy.async.shared::cta;" ::: "memory");
    }

#if VQ_TC
    if (wid == 0) {
        asm volatile("tcgen05.dealloc.cta_group::1.sync.aligned.b32 %0, %1;"
                     :: "r"(tmem_base), "r"(512u));
    }
#endif
}

extern "C" void kernel_launch(void* const* d_in, const int* in_sizes, int n_in,
                              void* d_out, int out_size) {
    const float* x   = (const float*)d_in[0];
    const float* emb = (const float*)d_in[1];
    float* out  = (float*)d_out;
    float* out0 = out;
    float* out1 = out + (size_t)NS * CC * VV;
    float* out2 = out1 + (size_t)NS * CC;

    cudaFuncSetAttribute(vq_tc_kernel, cudaFuncAttributeMaxDynamicSharedMemorySize,
                         SB_TOTAL);
    dim3 grid(NS / (MTILE * TILES), CC);
    vq_tc_kernel<<<grid, TPB, SB_TOTAL>>>(x, emb, out0, out1, out2);
}